// round 17
// baseline (speedup 1.0000x reference)
#include <cuda_runtime.h>
#include <cuda_fp16.h>
#include <cstdint>

// Problem constants
#define NB 2048
#define NT 64
#define NC 384
#define NH 12
#define ND 32
#define N3C 1152
#define MT 131072            // NB*NT rows
#define KDIM 384
#define SQ 50331648ull       // NB*NH*NT*ND
#define NTILES (NB * NH)     // 24576 attention tiles

// ---------------- device scratch (no allocation allowed) -------------------
__device__ __half g_qkvh[3 * SQ];                   // (3,B,H,T,D) fp16
__device__ float g_bias[NH * NT * NT];              // (H,T,T)
__device__ __half g_xh[(size_t)MT * NC];            // fp16 x
__device__ __half g_qwh[(size_t)N3C * NC];          // fp16 qkv_w
__device__ __half g_pwh[(size_t)NC * NC];           // fp16 proj_w
__device__ __half g_atth[(size_t)MT * NC];          // attn output (fp16)

// ---------------- helpers ---------------------------------------------------
__device__ __forceinline__ uint32_t smem_u32(const void* p) {
    uint32_t a;
    asm("{ .reg .u64 t; cvta.to.shared.u64 t, %1; cvt.u32.u64 %0, t; }"
        : "=r"(a) : "l"(p));
    return a;
}

#define CP_ASYNC16(dst, src) \
    asm volatile("cp.async.cg.shared.global [%0], [%1], 16;" \
                 :: "r"(dst), "l"(src) : "memory")
#define CP_COMMIT() asm volatile("cp.async.commit_group;" ::: "memory")
#define CP_WAIT(n)  asm volatile("cp.async.wait_group %0;" :: "n"(n) : "memory")

__device__ __forceinline__ void ldsm4(uint32_t& r0, uint32_t& r1,
                                      uint32_t& r2, uint32_t& r3, uint32_t a) {
    asm volatile("ldmatrix.sync.aligned.m8n8.x4.shared.b16 {%0,%1,%2,%3}, [%4];"
                 : "=r"(r0), "=r"(r1), "=r"(r2), "=r"(r3) : "r"(a));
}
__device__ __forceinline__ void ldsm4t(uint32_t& r0, uint32_t& r1,
                                       uint32_t& r2, uint32_t& r3, uint32_t a) {
    asm volatile("ldmatrix.sync.aligned.m8n8.x4.trans.shared.b16 {%0,%1,%2,%3}, [%4];"
                 : "=r"(r0), "=r"(r1), "=r"(r2), "=r"(r3) : "r"(a));
}

__device__ __forceinline__ void mma_f16(float c[4], const uint32_t a[4],
                                        const uint32_t b[2]) {
    asm volatile(
        "mma.sync.aligned.m16n8k16.row.col.f32.f16.f16.f32 "
        "{%0,%1,%2,%3},{%4,%5,%6,%7},{%8,%9},{%0,%1,%2,%3};"
        : "+f"(c[0]), "+f"(c[1]), "+f"(c[2]), "+f"(c[3])
        : "r"(a[0]), "r"(a[1]), "r"(a[2]), "r"(a[3]), "r"(b[0]), "r"(b[1]));
}

// ---------------------------------------------------------------------------
// fp32 -> fp16 conversion pass
// ---------------------------------------------------------------------------
__global__ void tohalf_kernel(const float* __restrict__ src,
                              __half* __restrict__ dst, int n4) {
    int i = blockIdx.x * 256 + threadIdx.x;
    if (i >= n4) return;
    float4 v = ((const float4*)src)[i];
    ((__half2*)dst)[2 * i]     = __floats2half2_rn(v.x, v.y);
    ((__half2*)dst)[2 * i + 1] = __floats2half2_rn(v.z, v.w);
}

// ---------------------------------------------------------------------------
// Bias gather
// ---------------------------------------------------------------------------
__global__ void bias_kernel(const float* __restrict__ rpb,
                            const int* __restrict__ rpi) {
    int i = blockIdx.x * 256 + threadIdx.x;
    if (i >= NH * NT * NT) return;
    int h  = i / (NT * NT);
    int qk = i - h * (NT * NT);
    g_bias[i] = rpb[rpi[qk] * NH + h];
}

// ---------------------------------------------------------------------------
// FP16 HMMA GEMM, R17: 128 threads (4 warps), warp tile 64x64, CTA 128x128.
// LDS:tensor = 1.0 (was 1.5). Regs ~170 < 256 budget at occ 2.
// BK=64 halfs (128B swizzled rows), 3-stage cp.async pipeline, 1 sync/iter.
// EPI==0: write fp16 q/k/v (q scaled). EPI==1: fp32 out (+bias).
// ---------------------------------------------------------------------------
#define HSTG 32768               // A 16KB + W 16KB per stage
#define SMH (3 * HSTG)           // 96 KB

template <int EPI>
__global__ void __launch_bounds__(128, 2)
h16_gemm(const __half* __restrict__ A, const __half* __restrict__ W,
         const float* __restrict__ bias, float* __restrict__ out) {
    extern __shared__ char smem[];
    const uint32_t sb = smem_u32(smem);

    const int tid  = threadIdx.x;
    const int warp = tid >> 5;
    const int lane = tid & 31;
    const int m0 = blockIdx.y * 128;
    const int n0 = blockIdx.x * 128;

    const int wm = (warp >> 1) * 64;    // 0 or 64
    const int wn = (warp & 1) * 64;     // 0 or 64

    // loaders: each thread owns one full 128B row of A and one of W
    const __half* Ap = A + (size_t)(m0 + tid) * KDIM;
    const __half* Wp = W + (size_t)(n0 + tid) * KDIM;
    const uint32_t lbase = tid * 128;
    const int lsw = tid & 7;

    auto fill = [&](int kc, int s) {
        const uint32_t base = sb + s * HSTG;
#pragma unroll
        for (int c = 0; c < 8; c++) {
            const uint32_t off = lbase + (((uint32_t)(c ^ lsw)) << 4);
            CP_ASYNC16(base + off,         Ap + kc * 64 + c * 8);
            CP_ASYNC16(base + 16384 + off, Wp + kc * 64 + c * 8);
        }
    };

    float acc[4][8][4];
#pragma unroll
    for (int i = 0; i < 4; i++)
#pragma unroll
        for (int j = 0; j < 8; j++)
#pragma unroll
            for (int r = 0; r < 4; r++) acc[i][j][r] = 0.0f;

    const int mat = lane >> 3;      // 0..3
    const int mr  = lane & 7;       // 0..7

    fill(0, 0); CP_COMMIT();
    fill(1, 1); CP_COMMIT();

    int scur = 0;
    int snxt = 2;
    for (int kc = 0; kc < 6; ++kc) {
        if (kc + 2 < 6) { CP_WAIT(1); } else { CP_WAIT(0); }
        __syncthreads();
        if (kc + 2 < 6) {
            fill(kc + 2, snxt);
            CP_COMMIT();
        }

        const uint32_t smA = sb + scur * HSTG;
        const uint32_t smW = smA + 16384;
        scur = (scur + 1 == 3) ? 0 : scur + 1;
        snxt = (snxt + 1 == 3) ? 0 : snxt + 1;

#pragma unroll
        for (int kg = 0; kg < 4; kg++) {   // 4 x k16 per BK=64
            // A fragments: 4 m16 tiles
            uint32_t af[4][4];
            const uint32_t achunk = ((uint32_t)(kg * 2 + (mat >> 1)) ^ (uint32_t)mr) << 4;
            const uint32_t arow   = wm + ((mat & 1) << 3) + mr;
#pragma unroll
            for (int tm = 0; tm < 4; tm++) {
                const uint32_t ad = smA + (arow + tm * 16) * 128 + achunk;
                ldsm4(af[tm][0], af[tm][1], af[tm][2], af[tm][3], ad);
            }
            // B fragments: 8 n8 tiles in 4 ldsm groups (keeps regs low)
            const uint32_t bchunk = ((uint32_t)(kg * 2 + (mat & 1)) ^ (uint32_t)mr) << 4;
#pragma unroll
            for (int p = 0; p < 4; p++) {
                const uint32_t brow = wn + (2 * p + (mat >> 1)) * 8 + mr;
                const uint32_t bd = smW + brow * 128 + bchunk;
                uint32_t t0, t1, t2, t3;
                ldsm4(t0, t1, t2, t3, bd);
                uint32_t b0[2] = {t0, t1}, b1[2] = {t2, t3};
#pragma unroll
                for (int tm = 0; tm < 4; tm++) {
                    mma_f16(acc[tm][2 * p],     af[tm], b0);
                    mma_f16(acc[tm][2 * p + 1], af[tm], b1);
                }
            }
        }
    }

    const int rA = lane >> 2;
    const int cA = lane & 3;
#pragma unroll
    for (int tm = 0; tm < 4; tm++) {
#pragma unroll
        for (int tn = 0; tn < 8; tn++) {
#pragma unroll
            for (int half = 0; half < 2; half++) {
                const int m = m0 + wm + tm * 16 + rA + half * 8;
                const int n = n0 + wn + tn * 8 + cA * 2;
                float v0 = acc[tm][tn][half * 2 + 0] + bias[n];
                float v1 = acc[tm][tn][half * 2 + 1] + bias[n + 1];
                if (EPI == 0) {
                    const int s   = n / NC;
                    const int rem = n - s * NC;
                    const int h   = rem >> 5;
                    const int d0  = rem & 31;
                    if (s == 0) {
                        const float sc = 0.17677669529663687f;  // 1/sqrt(32)
                        v0 *= sc; v1 *= sc;
                    }
                    const int b = m >> 6;
                    const int t = m & 63;
                    __half* dst = g_qkvh + (size_t)s * SQ +
                                  (((size_t)(b * NH + h)) * NT + t) * ND + d0;
                    *(__half2*)dst = __floats2half2_rn(v0, v1);
                } else {
                    *(float2*)(out + (size_t)m * NC + n) = make_float2(v0, v1);
                }
            }
        }
    }
}

// ---------------------------------------------------------------------------
// PERSISTENT attention (R16 version — unchanged)
// ---------------------------------------------------------------------------
#define STAGE_BYTES 15360
#define OFF_K 0
#define OFF_Q 5120
#define OFF_V 10240
#define OFF_SS (2 * STAGE_BYTES)            // 30720
#define ATTN_SMEM (OFF_SS + 64 * 68 * 4)    // 48128

__global__ void __launch_bounds__(256) attn_kernel() {
    __shared__ __align__(16) char sm[ATTN_SMEM];
    const uint32_t sb = smem_u32(sm);
    float* Ssp = (float*)(sm + OFF_SS);     // [64][68]

    const int tid = threadIdx.x;
    const int lane = tid & 31;
    const int warp = tid >> 5;
    const int rA = lane >> 2;
    const int cA = lane & 3;
    const int wm = (warp >> 1) * 16;
    const int wn = (warp & 1) * 32;
    const int wn2 = (warp & 1) * 16;
    const int mat = lane >> 3;
    const int mr  = lane & 7;

    const int lrow = tid >> 2;
    const int lcb  = tid & 3;
    const uint32_t lsoff = lrow * 80 + lcb * 16;
    const size_t lgoff = (size_t)lrow * 32 + lcb * 8;

    auto prefetch = [&](int bh, int s) {
        const uint32_t base = sb + s * STAGE_BYTES;
        const size_t tb = (size_t)bh * NT * ND;
        CP_ASYNC16(base + OFF_K + lsoff, g_qkvh + SQ + tb + lgoff);
        CP_ASYNC16(base + OFF_Q + lsoff, g_qkvh + tb + lgoff);
        CP_ASYNC16(base + OFF_V + lsoff, g_qkvh + 2 * SQ + tb + lgoff);
    };

    const uint32_t aoff = ((uint32_t)(mat >> 1)) << 4;
    const uint32_t boff = ((uint32_t)(mat & 1)) << 4;

    int tile = blockIdx.x;
    if (tile >= NTILES) return;

    prefetch(tile, 0); CP_COMMIT();

    int s = 0;
    for (; tile < NTILES; tile += gridDim.x, s ^= 1) {
        const int nxt = tile + gridDim.x;
        const int h = tile % NH;
        const int b = tile / NH;

        __syncthreads();
        const bool has_nxt = (nxt < NTILES);
        if (has_nxt) { prefetch(nxt, s ^ 1); CP_COMMIT(); }

        const float* bp = g_bias + h * NT * NT;
        float2 bzv[4][2];
#pragma unroll
        for (int tn = 0; tn < 4; tn++)
#pragma unroll
            for (int half = 0; half < 2; half++) {
                const int m = wm + rA + half * 8;
                const int n = wn + tn * 8 + cA * 2;
                bzv[tn][half] = *(const float2*)(bp + m * NT + n);
            }

        if (has_nxt) { CP_WAIT(1); } else { CP_WAIT(0); }
        __syncthreads();

        const uint32_t stg = sb + s * STAGE_BYTES;
        const uint32_t sK = stg + OFF_K;
        const uint32_t sQ = stg + OFF_Q;
        const uint32_t sV = stg + OFF_V;
        const uint32_t sP = stg;

        const uint32_t qrow = sQ + (uint32_t)(wm + ((mat & 1) << 3) + mr) * 80;
        const uint32_t prow = sP + (uint32_t)(wm + ((mat & 1) << 3) + mr) * 144;

        float sc_[4][4];
#pragma unroll
        for (int i = 0; i < 4; i++)
#pragma unroll
            for (int r = 0; r < 4; r++) sc_[i][r] = 0.0f;

#pragma unroll
        for (int ks = 0; ks < 2; ks++) {
            uint32_t a[4];
            ldsm4(a[0], a[1], a[2], a[3], qrow + ks * 32 + aoff);
#pragma unroll
            for (int p = 0; p < 2; p++) {
                const uint32_t brow = sK +
                    (uint32_t)(wn + (2 * p + (mat >> 1)) * 8 + mr) * 80;
                uint32_t t0, t1, t2, t3;
                ldsm4(t0, t1, t2, t3, brow + ks * 32 + boff);
                uint32_t b0[2] = {t0, t1}, b1[2] = {t2, t3};
                mma_f16(sc_[2 * p],     a, b0);
                mma_f16(sc_[2 * p + 1], a, b1);
            }
        }

#pragma unroll
        for (int tn = 0; tn < 4; tn++) {
#pragma unroll
            for (int half = 0; half < 2; half++) {
                const int m = wm + rA + half * 8;
                const int n = wn + tn * 8 + cA * 2;
                *(float2*)&Ssp[m * 68 + n] =
                    make_float2(sc_[tn][half * 2 + 0] + bzv[tn][half].x,
                                sc_[tn][half * 2 + 1] + bzv[tn][half].y);
            }
        }
        __syncthreads();

#pragma unroll
        for (int r = warp * 8; r < warp * 8 + 8; ++r) {
            float e0 = __expf(Ssp[r * 68 + lane]);
            float e1 = __expf(Ssp[r * 68 + lane + 32]);
            float smv = e0 + e1;
#pragma unroll
            for (int o = 16; o; o >>= 1)
                smv += __shfl_xor_sync(0xffffffffu, smv, o);
            float inv = 1.0f / smv;
            __half* pr = (__half*)(sm + s * STAGE_BYTES) + r * 72;
            pr[lane]      = __float2half_rn(e0 * inv);
            pr[lane + 32] = __float2half_rn(e1 * inv);
        }
        __syncthreads();

        float oc[2][4];
#pragma unroll
        for (int i = 0; i < 2; i++)
#pragma unroll
            for (int r = 0; r < 4; r++) oc[i][r] = 0.0f;

#pragma unroll
        for (int ks = 0; ks < 4; ks++) {
            uint32_t a[4];
            ldsm4(a[0], a[1], a[2], a[3], prow + ks * 32 + aoff);
            uint32_t t0, t1, t2, t3;
            const uint32_t vb = sV +
                (uint32_t)(ks * 16 + ((mat & 1) << 3) + mr) * 80 +
                (uint32_t)(wn2 + ((mat >> 1) << 3)) * 2;
            ldsm4t(t0, t1, t2, t3, vb);
            uint32_t b0[2] = {t0, t1}, b1[2] = {t2, t3};
            mma_f16(oc[0], a, b0);
            mma_f16(oc[1], a, b1);
        }

#pragma unroll
        for (int tn = 0; tn < 2; tn++) {
#pragma unroll
            for (int half = 0; half < 2; half++) {
                const int t = wm + rA + half * 8;
                const int d = wn2 + tn * 8 + cA * 2;
                __half2 hw = __floats2half2_rn(oc[tn][half * 2 + 0],
                                               oc[tn][half * 2 + 1]);
                *(__half2*)&g_atth[((size_t)(b * NT + t)) * NC + h * ND + d] = hw;
            }
        }
    }
}

// ---------------------------------------------------------------------------
// Launch  (order arranged so launch #4 = h16_gemm<0> for ncu capture)
// ---------------------------------------------------------------------------
extern "C" void kernel_launch(void* const* d_in, const int* in_sizes, int n_in,
                              void* d_out, int out_size) {
    const float* x      = (const float*)d_in[0];
    const float* qkv_w  = (const float*)d_in[1];
    const float* qkv_b  = (const float*)d_in[2];
    const float* proj_w = (const float*)d_in[3];
    const float* proj_b = (const float*)d_in[4];
    const float* rpb    = (const float*)d_in[5];
    const int*   rpi    = (const int*)d_in[6];
    float* out = (float*)d_out;

    cudaFuncSetAttribute(h16_gemm<0>, cudaFuncAttributeMaxDynamicSharedMemorySize, SMH);
    cudaFuncSetAttribute(h16_gemm<1>, cudaFuncAttributeMaxDynamicSharedMemorySize, SMH);

    __half *xh, *qwh, *pwh, *atth;
    cudaGetSymbolAddress((void**)&xh,   g_xh);
    cudaGetSymbolAddress((void**)&qwh,  g_qwh);
    cudaGetSymbolAddress((void**)&pwh,  g_pwh);
    cudaGetSymbolAddress((void**)&atth, g_atth);

    int nsm = 148, occ = 4;
    cudaDeviceGetAttribute(&nsm, cudaDevAttrMultiProcessorCount, 0);
    cudaOccupancyMaxActiveBlocksPerMultiprocessor(&occ, attn_kernel, 256, 0);
    if (occ < 1) occ = 1;
    int attn_grid = nsm * occ;
    if (attn_grid > NTILES) attn_grid = NTILES;

    // fp16 conversions (launches 1-3)
    {
        int n4 = (MT * NC) / 4;
        tohalf_kernel<<<(n4 + 255) / 256, 256>>>(x, xh, n4);
        n4 = (N3C * NC) / 4;
        tohalf_kernel<<<(n4 + 255) / 256, 256>>>(qkv_w, qwh, n4);
        n4 = (NC * NC) / 4;
        tohalf_kernel<<<(n4 + 255) / 256, 256>>>(proj_w, pwh, n4);
    }

    // launch 4: the big QKV GEMM (profiled slot)
    dim3 g1(N3C / 128, MT / 128);   // (9, 1024)
    h16_gemm<0><<<g1, 128, SMH>>>(xh, qwh, qkv_b, nullptr);

    // launch 5: bias gather
    bias_kernel<<<(NH * NT * NT + 255) / 256, 256>>>(rpb, rpi);

    // launch 6: persistent attention
    attn_kernel<<<attn_grid, 256>>>();

    // launch 7: projection GEMM
    dim3 g2(NC / 128, MT / 128);    // (3, 1024)
    h16_gemm<1><<<g2, 128, SMH>>>(atth, pwh, proj_b, out);
}